// round 16
// baseline (speedup 1.0000x reference)
#include <cuda_runtime.h>
#include <cuda_fp16.h>
#include <cstdint>
#include <math.h>

// ---------------------------------------------------------------------------
// NormLinearAttention  B=2 N=2048 D=1024 H=16 DH=64
// R16 (= R15 resubmit after infra failure): ALL matmuls on fp16 m16n8k16:
//   - hgemm_nt (proven R11, 3-stage cp.async ring) for the two big GEMMs
//   - kv_kernel tensorized (k'^T v via mma, fp32 accum, fp32 partials)
//   - qout tensorized fp16 (KV^T stored fp16)
// ---------------------------------------------------------------------------

#define Bb 2
#define Nn 2048
#define Dd 1024
#define Hh 16
#define DH 64
#define MROWS (Bb*Nn)        // 4096

__device__ float  g_qkvu[(size_t)MROWS * 4 * Dd];    // 64 MB
__device__ float  g_kvp[8 * 32 * 64 * 128];           // 8 MB partial KV^T [e][dd]
__device__ __half g_kvTh[32 * 64 * 128];              // 0.5 MB reduced KV^T (fp16)
__device__ float  g_attn[(size_t)MROWS * Dd];         // 16 MB
__device__ float2 g_trig[(size_t)Hh * Nn * DH];       // 16 MB
__device__ __half g_xh[(size_t)MROWS * Dd];           // 8 MB  x (fp16)
__device__ __half g_wqh[(size_t)4 * Dd * Dd];         // 8 MB  Wqkvu (fp16)
__device__ __half g_woh[(size_t)Dd * Dd];             // 2 MB  Wout (fp16)
__device__ __half g_normh[(size_t)MROWS * Dd];        // 8 MB  LN output (fp16)

// ---------------------------------------------------------------------------
// helpers
// ---------------------------------------------------------------------------
__device__ __forceinline__ void mma_f16(float* c, const uint32_t* a, const uint32_t* b) {
    asm volatile(
        "mma.sync.aligned.m16n8k16.row.col.f32.f16.f16.f32 "
        "{%0,%1,%2,%3}, {%4,%5,%6,%7}, {%8,%9}, {%0,%1,%2,%3};"
        : "+f"(c[0]), "+f"(c[1]), "+f"(c[2]), "+f"(c[3])
        : "r"(a[0]), "r"(a[1]), "r"(a[2]), "r"(a[3]), "r"(b[0]), "r"(b[1]));
}

__device__ __forceinline__ void cpa16(uint32_t dst, const void* src) {
    asm volatile("cp.async.cg.shared.global [%0], [%1], 16;" :: "r"(dst), "l"(src));
}
__device__ __forceinline__ void cpa_commit() { asm volatile("cp.async.commit_group;"); }
__device__ __forceinline__ void cpa_wait1()  { asm volatile("cp.async.wait_group 1;"); }

// ---------------------------------------------------------------------------
// fp32 -> fp16 conversion (elementwise)
// ---------------------------------------------------------------------------
__global__ __launch_bounds__(256)
void tohalf_kernel(const float4* __restrict__ src, __half2* __restrict__ dst, int n4)
{
    const int i = blockIdx.x * 256 + threadIdx.x;
    if (i < n4) {
        const float4 v = src[i];
        dst[2 * i]     = __floats2half2_rn(v.x, v.y);
        dst[2 * i + 1] = __floats2half2_rn(v.z, v.w);
    }
}

// ---------------------------------------------------------------------------
// FP16 GEMM (NT): C[m,n] = sum_k A[m,k]*B[n,k] + bias[n]; fp32 accum.
// (proven R11: 128x128 tile, BK=32, 3-stage cp.async ring, stride 40)
// ---------------------------------------------------------------------------
#define HBK 32
#define HSTR 40
#define H_MAT_HALF (128 * HSTR)
#define H_STG_HALF (2 * H_MAT_HALF)
#define H_STG_B (H_STG_HALF * 2)
#define H_SMEM_TOTAL (3 * H_STG_B)     // 61440 bytes

__global__ __launch_bounds__(256, 2)
void hgemm_nt(const __half* __restrict__ A, const __half* __restrict__ B,
              const float* __restrict__ bias, float* __restrict__ C,
              int M, int N, int K)
{
    extern __shared__ __half hsm[];

    const int tid = threadIdx.x;
    const int bm = blockIdx.y * 128;
    const int bn = blockIdx.x * 128;
    const int wid = tid >> 5, lane = tid & 31;
    const int g = lane >> 2, tg = lane & 3;
    const int wm = (wid >> 2) * 64;
    const int wn = (wid & 3) * 32;

    float acc[4][4][4];
#pragma unroll
    for (int mi = 0; mi < 4; mi++)
#pragma unroll
        for (int ni = 0; ni < 4; ni++)
#pragma unroll
            for (int j = 0; j < 4; j++) acc[mi][ni][j] = 0.f;

    const int lrow = tid >> 2;
    const int lc8 = (tid & 3) * 8;
    const __half* Ag = A + (size_t)(bm + lrow) * K + lc8;
    const __half* Bg = B + (size_t)(bn + lrow) * K + lc8;

    const uint32_t sbase = (uint32_t)__cvta_generic_to_shared(hsm);
    const uint32_t dA0 = (lrow * HSTR + lc8) * 2;
    const uint32_t dA1 = ((lrow + 64) * HSTR + lc8) * 2;
    const uint32_t dB = H_MAT_HALF * 2;

    const int nt = K / HBK;

#pragma unroll
    for (int s = 0; s < 2; s++) {
        const int koff = s * HBK;
        const uint32_t so = sbase + s * H_STG_B;
        cpa16(so + dA0, Ag + koff);
        cpa16(so + dA1, Ag + (size_t)64 * K + koff);
        cpa16(so + dB + dA0, Bg + koff);
        cpa16(so + dB + dA1, Bg + (size_t)64 * K + koff);
        cpa_commit();
    }

    int st = 0;
    for (int kt = 0; kt < nt; kt++) {
        cpa_wait1();
        __syncthreads();

        if (kt + 2 < nt) {
            const int koff = (kt + 2) * HBK;
            int sn = st + 2; if (sn >= 3) sn -= 3;
            const uint32_t so = sbase + sn * H_STG_B;
            cpa16(so + dA0, Ag + koff);
            cpa16(so + dA1, Ag + (size_t)64 * K + koff);
            cpa16(so + dB + dA0, Bg + koff);
            cpa16(so + dB + dA1, Bg + (size_t)64 * K + koff);
            cpa_commit();
        }

        const __half* a_s = hsm + st * H_STG_HALF;
        const __half* b_s = a_s + H_MAT_HALF;

#pragma unroll
        for (int ks = 0; ks < 2; ks++) {
            const int k0 = ks * 16;
            uint32_t af[4][4], bf[4][2];
#pragma unroll
            for (int mi = 0; mi < 4; mi++) {
                const int r0 = wm + mi * 16 + g;
                af[mi][0] = *(const uint32_t*)&a_s[r0 * HSTR + k0 + 2 * tg];
                af[mi][1] = *(const uint32_t*)&a_s[(r0 + 8) * HSTR + k0 + 2 * tg];
                af[mi][2] = *(const uint32_t*)&a_s[r0 * HSTR + k0 + 8 + 2 * tg];
                af[mi][3] = *(const uint32_t*)&a_s[(r0 + 8) * HSTR + k0 + 8 + 2 * tg];
            }
#pragma unroll
            for (int ni = 0; ni < 4; ni++) {
                const int c0 = wn + ni * 8 + g;
                bf[ni][0] = *(const uint32_t*)&b_s[c0 * HSTR + k0 + 2 * tg];
                bf[ni][1] = *(const uint32_t*)&b_s[c0 * HSTR + k0 + 8 + 2 * tg];
            }
#pragma unroll
            for (int mi = 0; mi < 4; mi++)
#pragma unroll
                for (int ni = 0; ni < 4; ni++)
                    mma_f16(acc[mi][ni], af[mi], bf[ni]);
        }
        if (++st == 3) st = 0;
    }

#pragma unroll
    for (int mi = 0; mi < 4; mi++) {
        const int row = bm + wm + mi * 16 + g;
#pragma unroll
        for (int ni = 0; ni < 4; ni++) {
            const int col = bn + wn + ni * 8 + 2 * tg;
            const float bx = bias[col], by = bias[col + 1];
            float2 v0 = make_float2(acc[mi][ni][0] + bx, acc[mi][ni][1] + by);
            float2 v1 = make_float2(acc[mi][ni][2] + bx, acc[mi][ni][3] + by);
            *(float2*)&C[(size_t)row * N + col] = v0;
            *(float2*)&C[(size_t)(row + 8) * N + col] = v1;
        }
    }
}

__device__ __forceinline__ float silu_f(float x) {
    return x / (1.f + expf(-x));
}

// ---------------------------------------------------------------------------
// trig table
// ---------------------------------------------------------------------------
__global__ __launch_bounds__(256)
void trig_kernel(const float* __restrict__ theta)
{
    const int idx = blockIdx.x * 256 + threadIdx.x;
    const int d = idx & 63;
    const int n = (idx >> 6) & 2047;
    const int h = idx >> 17;
    float sn, cs;
    sincosf(theta[h * DH + d] * (float)n, &sn, &cs);
    g_trig[idx] = make_float2(cs, sn);
}

// ---------------------------------------------------------------------------
// partial KV via fp16 mma: per (bh, chunk of 256 tokens):
// C[dd][e] += k'T[dd][tok] * vT[e][tok]  (mma row.col, K=16 tokens/step)
// stage stride 24 halves -> fragment banks 12g+tg mod 32 all-distinct.
// ---------------------------------------------------------------------------
#define KSTR 24

__global__ __launch_bounds__(256)
void kv_kernel()
{
    __shared__ __half skqT[128][KSTR];   // 6144 B  k'T [dd][tok]
    __shared__ __half svT[64][KSTR];     // 3072 B  vT  [e][tok]

    const int bh = blockIdx.x;
    const int b = bh >> 4, h = bh & 15;
    const int chunk = blockIdx.y;
    const int tid = threadIdx.x;
    const int wid = tid >> 5, lane = tid & 31;
    const int g = lane >> 2, tg = lane & 3;
    const int wm = (wid >> 1) * 32;      // dd: 0,32,64,96
    const int wn = (wid & 1) * 32;       // e : 0,32

    const float* base = g_qkvu + (size_t)b * Nn * 4096;
    const float2* trig = g_trig + (size_t)h * Nn * DH;

    float acc[2][4][4];
#pragma unroll
    for (int mi = 0; mi < 2; mi++)
#pragma unroll
        for (int ni = 0; ni < 4; ni++)
#pragma unroll
            for (int j = 0; j < 4; j++) acc[mi][ni][j] = 0.f;

    for (int n0 = chunk * 256; n0 < chunk * 256 + 256; n0 += 16) {
        __syncthreads();
#pragma unroll
        for (int it = 0; it < 4; it++) {
            const int item = tid + it * 256;     // 0..1023
            const int tok = item >> 6;
            const int d = item & 63;
            const int n = n0 + tok;
            const float kraw = base[(size_t)n * 4096 + Dd + h * DH + d];
            const float s = silu_f(kraw);
            const float2 t = trig[(size_t)n * DH + d];
            skqT[d][tok] = __float2half(s * t.x);
            skqT[DH + d][tok] = __float2half(s * t.y);
            svT[d][tok] = __float2half(base[(size_t)n * 4096 + 2 * Dd + h * DH + d]);
        }
        __syncthreads();

        uint32_t af[2][4], bf[4][2];
#pragma unroll
        for (int mi = 0; mi < 2; mi++) {
            const int r0 = wm + mi * 16 + g;
            af[mi][0] = *(const uint32_t*)&skqT[r0][2 * tg];
            af[mi][1] = *(const uint32_t*)&skqT[r0 + 8][2 * tg];
            af[mi][2] = *(const uint32_t*)&skqT[r0][8 + 2 * tg];
            af[mi][3] = *(const uint32_t*)&skqT[r0 + 8][8 + 2 * tg];
        }
#pragma unroll
        for (int ni = 0; ni < 4; ni++) {
            const int c0 = wn + ni * 8 + g;
            bf[ni][0] = *(const uint32_t*)&svT[c0][2 * tg];
            bf[ni][1] = *(const uint32_t*)&svT[c0][8 + 2 * tg];
        }
#pragma unroll
        for (int mi = 0; mi < 2; mi++)
#pragma unroll
            for (int ni = 0; ni < 4; ni++)
                mma_f16(acc[mi][ni], af[mi], bf[ni]);
    }

    // write partials transposed [e][dd] (fp32, deterministic reduce after)
    float* outp = g_kvp + (size_t)chunk * (32 * 8192) + (size_t)bh * 8192;
#pragma unroll
    for (int mi = 0; mi < 2; mi++) {
        const int dd0 = wm + mi * 16 + g;
#pragma unroll
        for (int ni = 0; ni < 4; ni++) {
            const int e0 = wn + ni * 8 + 2 * tg;
            outp[e0 * 128 + dd0]           = acc[mi][ni][0];
            outp[(e0 + 1) * 128 + dd0]     = acc[mi][ni][1];
            outp[e0 * 128 + dd0 + 8]       = acc[mi][ni][2];
            outp[(e0 + 1) * 128 + dd0 + 8] = acc[mi][ni][3];
        }
    }
}

__global__ __launch_bounds__(256)
void kv_reduce()
{
    const int i = blockIdx.x * 256 + threadIdx.x;
    float s = 0.f;
#pragma unroll
    for (int c = 0; c < 8; c++)
        s += g_kvp[(size_t)c * (32 * 8192) + i];
    g_kvTh[i] = __float2half(s);
}

// ---------------------------------------------------------------------------
// qout (fp16 mma): attn[tok, h*64+e] = sum_dd q'[tok,dd] * KVT[e,dd]
// smem stride 136 halves -> fragment banks 4g+tg mod 32 all-distinct.
// ---------------------------------------------------------------------------
#define QH 136
#define QOUT_SMEM ((128 + 64) * QH * 2)   // 52224 B

__global__ __launch_bounds__(256)
void qout_kernel()
{
    extern __shared__ __half qsmh[];
    __half* sQh = qsmh;                  // [128 tok][QH]
    __half* sKVth = qsmh + 128 * QH;     // [64 e][QH]

    const int bh = blockIdx.x;
    const int b = bh >> 4, h = bh & 15;
    const int n0 = blockIdx.y * 128;
    const int tid = threadIdx.x;
    const int wid = tid >> 5, lane = tid & 31;
    const int g = lane >> 2, tg = lane & 3;

    // load KV^T [64][128] halves -> sKVth (8 halves per uint4)
    {
        const uint4* src = (const uint4*)(g_kvTh + (size_t)bh * 8192);
        for (int i = tid; i < 1024; i += 256) {
            const int e = i >> 4;
            const int dc = (i & 15) * 8;
            *(uint4*)&sKVth[e * QH + dc] = src[i];
        }
    }

    // build q' for 128 tokens, fp16 (half2 stores)
    {
        const int token = tid >> 1;
        const int d0 = (tid & 1) * 32;
        const int n = n0 + token;
        const float* qrow = g_qkvu + ((size_t)b * Nn + n) * 4096 + h * DH + d0;
        const float2* trow = g_trig + ((size_t)h * Nn + n) * DH + d0;
        __half* dst = sQh + token * QH;
#pragma unroll
        for (int d = 0; d < 32; d += 2) {
            const float s0 = silu_f(qrow[d]);
            const float s1 = silu_f(qrow[d + 1]);
            const float2 t0 = trow[d];
            const float2 t1 = trow[d + 1];
            *(__half2*)&dst[d0 + d] = __floats2half2_rn(s0 * t0.x, s1 * t1.x);
            *(__half2*)&dst[DH + d0 + d] = __floats2half2_rn(s0 * t0.y, s1 * t1.y);
        }
    }
    __syncthreads();

    const int wm = (wid >> 1) * 32;
    const int wn = (wid & 1) * 32;

    float acc[2][4][4];
#pragma unroll
    for (int mi = 0; mi < 2; mi++)
#pragma unroll
        for (int ni = 0; ni < 4; ni++)
#pragma unroll
            for (int j = 0; j < 4; j++) acc[mi][ni][j] = 0.f;

#pragma unroll
    for (int k0 = 0; k0 < 128; k0 += 16) {
        uint32_t af[2][4], bf[4][2];
#pragma unroll
        for (int mi = 0; mi < 2; mi++) {
            const int r0 = wm + mi * 16 + g;
            af[mi][0] = *(const uint32_t*)&sQh[r0 * QH + k0 + 2 * tg];
            af[mi][1] = *(const uint32_t*)&sQh[(r0 + 8) * QH + k0 + 2 * tg];
            af[mi][2] = *(const uint32_t*)&sQh[r0 * QH + k0 + 8 + 2 * tg];
            af[mi][3] = *(const uint32_t*)&sQh[(r0 + 8) * QH + k0 + 8 + 2 * tg];
        }
#pragma unroll
        for (int ni = 0; ni < 4; ni++) {
            const int c0 = wn + ni * 8 + g;
            bf[ni][0] = *(const uint32_t*)&sKVth[c0 * QH + k0 + 2 * tg];
            bf[ni][1] = *(const uint32_t*)&sKVth[c0 * QH + k0 + 8 + 2 * tg];
        }
#pragma unroll
        for (int mi = 0; mi < 2; mi++)
#pragma unroll
            for (int ni = 0; ni < 4; ni++)
                mma_f16(acc[mi][ni], af[mi], bf[ni]);
    }

#pragma unroll
    for (int mi = 0; mi < 2; mi++) {
        const int row = n0 + wm + mi * 16 + g;
        float* base0 = g_attn + ((size_t)b * Nn + row) * Dd + h * DH;
        float* base1 = g_attn + ((size_t)b * Nn + row + 8) * Dd + h * DH;
#pragma unroll
        for (int ni = 0; ni < 4; ni++) {
            const int col = wn + ni * 8 + 2 * tg;
            *(float2*)&base0[col] = make_float2(acc[mi][ni][0], acc[mi][ni][1]);
            *(float2*)&base1[col] = make_float2(acc[mi][ni][2], acc[mi][ni][3]);
        }
    }
}

// ---------------------------------------------------------------------------
// LayerNorm + *u ; emits fp16 for GEMM2
// ---------------------------------------------------------------------------
__device__ __forceinline__ float block_reduce_256(float v, float* sred, int tid)
{
#pragma unroll
    for (int o = 16; o; o >>= 1) v += __shfl_xor_sync(0xffffffffu, v, o);
    if ((tid & 31) == 0) sred[tid >> 5] = v;
    __syncthreads();
    float r;
    if (tid < 32) {
        float t = (tid < 8) ? sred[tid] : 0.f;
#pragma unroll
        for (int o = 4; o; o >>= 1) t += __shfl_xor_sync(0xffffffffu, t, o);
        if (tid == 0) sred[0] = t;
    }
    __syncthreads();
    r = sred[0];
    __syncthreads();
    return r;
}

__global__ __launch_bounds__(256)
void ln_kernel(const float* __restrict__ ln_w, const float* __restrict__ ln_b)
{
    __shared__ float sred[8];
    const int row = blockIdx.x;
    const int tid = threadIdx.x;
    const int b = row >> 11, n = row & 2047;

    const float4 v = ((const float4*)(g_attn + (size_t)row * Dd))[tid];
    float s = v.x + v.y + v.z + v.w;
    const float mu = block_reduce_256(s, sred, tid) * (1.f / 1024.f);

    const float dx = v.x - mu, dy = v.y - mu, dz = v.z - mu, dw = v.w - mu;
    float s2 = dx * dx + dy * dy + dz * dz + dw * dw;
    const float var = block_reduce_256(s2, sred, tid) * (1.f / 1024.f);
    const float rstd = rsqrtf(var + 1e-5f);

    const float4 w4 = ((const float4*)ln_w)[tid];
    const float4 b4 = ((const float4*)ln_b)[tid];
    const float4 u4 = ((const float4*)(g_qkvu + ((size_t)b * Nn + n) * 4096 + 3 * Dd))[tid];

    const float ox = (dx * rstd * w4.x + b4.x) * u4.x;
    const float oy = (dy * rstd * w4.y + b4.y) * u4.y;
    const float oz = (dz * rstd * w4.z + b4.z) * u4.z;
    const float ow = (dw * rstd * w4.w + b4.w) * u4.w;

    __half2* dsth = (__half2*)(g_normh + (size_t)row * Dd);
    dsth[2 * tid]     = __floats2half2_rn(ox, oy);
    dsth[2 * tid + 1] = __floats2half2_rn(oz, ow);
}

// ---------------------------------------------------------------------------
extern "C" void kernel_launch(void* const* d_in, const int* in_sizes, int n_in,
                              void* d_out, int out_size)
{
    const float* x     = (const float*)d_in[0];
    const float* Wqkvu = (const float*)d_in[2];
    const float* bqkvu = (const float*)d_in[3];
    const float* Wout  = (const float*)d_in[4];
    const float* bout  = (const float*)d_in[5];
    const float* theta = (const float*)d_in[6];
    const float* ln_w  = (const float*)d_in[7];
    const float* ln_b  = (const float*)d_in[8];
    float* out = (float*)d_out;

    float *qkvu_p;
    __half *xh_p, *wqh_p, *woh_p, *normh_p;
    cudaGetSymbolAddress((void**)&qkvu_p, g_qkvu);
    cudaGetSymbolAddress((void**)&xh_p, g_xh);
    cudaGetSymbolAddress((void**)&wqh_p, g_wqh);
    cudaGetSymbolAddress((void**)&woh_p, g_woh);
    cudaGetSymbolAddress((void**)&normh_p, g_normh);

    cudaFuncSetAttribute(qout_kernel, cudaFuncAttributeMaxDynamicSharedMemorySize,
                         QOUT_SMEM);
    cudaFuncSetAttribute(hgemm_nt, cudaFuncAttributeMaxDynamicSharedMemorySize,
                         H_SMEM_TOTAL);

    // 0. trig table + fp16 conversion of GEMM operands
    trig_kernel<<<(Hh * Nn * DH) / 256, 256>>>(theta);
    tohalf_kernel<<<(MROWS * Dd / 4 + 255) / 256, 256>>>((const float4*)x, (__half2*)xh_p, MROWS * Dd / 4);
    tohalf_kernel<<<(4 * Dd * Dd / 4 + 255) / 256, 256>>>((const float4*)Wqkvu, (__half2*)wqh_p, 4 * Dd * Dd / 4);
    tohalf_kernel<<<(Dd * Dd / 4 + 255) / 256, 256>>>((const float4*)Wout, (__half2*)woh_p, Dd * Dd / 4);

    // 1. qkvu = x @ Wqkvu^T + bqkvu   [4096 x 4096]  (fp16 mma, 3-stage)
    {
        dim3 grid(4096 / 128, MROWS / 128);
        hgemm_nt<<<grid, 256, H_SMEM_TOTAL>>>(xh_p, wqh_p, bqkvu, qkvu_p, MROWS, 4096, 1024);
    }
    // 2-3. KV^T partials (fp16 mma) + deterministic reduce -> fp16
    {
        dim3 grid(32, 8);
        kv_kernel<<<grid, 256>>>();
        kv_reduce<<<1024, 256>>>();
    }
    // 4. attn = q' @ KV  (fp16 mma)
    {
        dim3 grid(32, Nn / 128);
        qout_kernel<<<grid, 256, QOUT_SMEM>>>();
    }
    // 5. LayerNorm + *u -> fp16
    ln_kernel<<<MROWS, 256>>>(ln_w, ln_b);

    // 6. out = norm @ Wout^T + bout   [4096 x 1024]  (fp16 mma, 3-stage)
    {
        dim3 grid(1024 / 128, MROWS / 128);
        hgemm_nt<<<grid, 256, H_SMEM_TOTAL>>>(normh_p, woh_p, bout, out, MROWS, 1024, 1024);
    }
}

// round 17
// speedup vs baseline: 1.4255x; 1.4255x over previous
#include <cuda_runtime.h>
#include <cuda_fp16.h>
#include <cstdint>
#include <math.h>

// ---------------------------------------------------------------------------
// NormLinearAttention  B=2 N=2048 D=1024 H=16 DH=64
// R17 (= R15/R16 source, re-bench): R16's +98us tracked the tohalf clock
// canary (4.64us@905GB/s -> 5.79us@725GB/s on identical code) => run-level
// DVFS noise, not the kernel. Re-measuring the identical binary.
//   - hgemm_nt (proven R11, 3-stage cp.async ring) for the two big GEMMs
//   - kv_kernel tensorized (k'^T v via fp16 mma, fp32 accum/partials)
//   - qout tensorized fp16 (KV^T stored fp16)
// ---------------------------------------------------------------------------

#define Bb 2
#define Nn 2048
#define Dd 1024
#define Hh 16
#define DH 64
#define MROWS (Bb*Nn)        // 4096

__device__ float  g_qkvu[(size_t)MROWS * 4 * Dd];    // 64 MB
__device__ float  g_kvp[8 * 32 * 64 * 128];           // 8 MB partial KV^T [e][dd]
__device__ __half g_kvTh[32 * 64 * 128];              // 0.5 MB reduced KV^T (fp16)
__device__ float  g_attn[(size_t)MROWS * Dd];         // 16 MB
__device__ float2 g_trig[(size_t)Hh * Nn * DH];       // 16 MB
__device__ __half g_xh[(size_t)MROWS * Dd];           // 8 MB  x (fp16)
__device__ __half g_wqh[(size_t)4 * Dd * Dd];         // 8 MB  Wqkvu (fp16)
__device__ __half g_woh[(size_t)Dd * Dd];             // 2 MB  Wout (fp16)
__device__ __half g_normh[(size_t)MROWS * Dd];        // 8 MB  LN output (fp16)

// ---------------------------------------------------------------------------
// helpers
// ---------------------------------------------------------------------------
__device__ __forceinline__ void mma_f16(float* c, const uint32_t* a, const uint32_t* b) {
    asm volatile(
        "mma.sync.aligned.m16n8k16.row.col.f32.f16.f16.f32 "
        "{%0,%1,%2,%3}, {%4,%5,%6,%7}, {%8,%9}, {%0,%1,%2,%3};"
        : "+f"(c[0]), "+f"(c[1]), "+f"(c[2]), "+f"(c[3])
        : "r"(a[0]), "r"(a[1]), "r"(a[2]), "r"(a[3]), "r"(b[0]), "r"(b[1]));
}

__device__ __forceinline__ void cpa16(uint32_t dst, const void* src) {
    asm volatile("cp.async.cg.shared.global [%0], [%1], 16;" :: "r"(dst), "l"(src));
}
__device__ __forceinline__ void cpa_commit() { asm volatile("cp.async.commit_group;"); }
__device__ __forceinline__ void cpa_wait1()  { asm volatile("cp.async.wait_group 1;"); }

// ---------------------------------------------------------------------------
// fp32 -> fp16 conversion (elementwise)
// ---------------------------------------------------------------------------
__global__ __launch_bounds__(256)
void tohalf_kernel(const float4* __restrict__ src, __half2* __restrict__ dst, int n4)
{
    const int i = blockIdx.x * 256 + threadIdx.x;
    if (i < n4) {
        const float4 v = src[i];
        dst[2 * i]     = __floats2half2_rn(v.x, v.y);
        dst[2 * i + 1] = __floats2half2_rn(v.z, v.w);
    }
}

// ---------------------------------------------------------------------------
// FP16 GEMM (NT): C[m,n] = sum_k A[m,k]*B[n,k] + bias[n]; fp32 accum.
// (proven R11: 128x128 tile, BK=32, 3-stage cp.async ring, stride 40)
// ---------------------------------------------------------------------------
#define HBK 32
#define HSTR 40
#define H_MAT_HALF (128 * HSTR)
#define H_STG_HALF (2 * H_MAT_HALF)
#define H_STG_B (H_STG_HALF * 2)
#define H_SMEM_TOTAL (3 * H_STG_B)     // 61440 bytes

__global__ __launch_bounds__(256, 2)
void hgemm_nt(const __half* __restrict__ A, const __half* __restrict__ B,
              const float* __restrict__ bias, float* __restrict__ C,
              int M, int N, int K)
{
    extern __shared__ __half hsm[];

    const int tid = threadIdx.x;
    const int bm = blockIdx.y * 128;
    const int bn = blockIdx.x * 128;
    const int wid = tid >> 5, lane = tid & 31;
    const int g = lane >> 2, tg = lane & 3;
    const int wm = (wid >> 2) * 64;
    const int wn = (wid & 3) * 32;

    float acc[4][4][4];
#pragma unroll
    for (int mi = 0; mi < 4; mi++)
#pragma unroll
        for (int ni = 0; ni < 4; ni++)
#pragma unroll
            for (int j = 0; j < 4; j++) acc[mi][ni][j] = 0.f;

    const int lrow = tid >> 2;
    const int lc8 = (tid & 3) * 8;
    const __half* Ag = A + (size_t)(bm + lrow) * K + lc8;
    const __half* Bg = B + (size_t)(bn + lrow) * K + lc8;

    const uint32_t sbase = (uint32_t)__cvta_generic_to_shared(hsm);
    const uint32_t dA0 = (lrow * HSTR + lc8) * 2;
    const uint32_t dA1 = ((lrow + 64) * HSTR + lc8) * 2;
    const uint32_t dB = H_MAT_HALF * 2;

    const int nt = K / HBK;

#pragma unroll
    for (int s = 0; s < 2; s++) {
        const int koff = s * HBK;
        const uint32_t so = sbase + s * H_STG_B;
        cpa16(so + dA0, Ag + koff);
        cpa16(so + dA1, Ag + (size_t)64 * K + koff);
        cpa16(so + dB + dA0, Bg + koff);
        cpa16(so + dB + dA1, Bg + (size_t)64 * K + koff);
        cpa_commit();
    }

    int st = 0;
    for (int kt = 0; kt < nt; kt++) {
        cpa_wait1();
        __syncthreads();

        if (kt + 2 < nt) {
            const int koff = (kt + 2) * HBK;
            int sn = st + 2; if (sn >= 3) sn -= 3;
            const uint32_t so = sbase + sn * H_STG_B;
            cpa16(so + dA0, Ag + koff);
            cpa16(so + dA1, Ag + (size_t)64 * K + koff);
            cpa16(so + dB + dA0, Bg + koff);
            cpa16(so + dB + dA1, Bg + (size_t)64 * K + koff);
            cpa_commit();
        }

        const __half* a_s = hsm + st * H_STG_HALF;
        const __half* b_s = a_s + H_MAT_HALF;

#pragma unroll
        for (int ks = 0; ks < 2; ks++) {
            const int k0 = ks * 16;
            uint32_t af[4][4], bf[4][2];
#pragma unroll
            for (int mi = 0; mi < 4; mi++) {
                const int r0 = wm + mi * 16 + g;
                af[mi][0] = *(const uint32_t*)&a_s[r0 * HSTR + k0 + 2 * tg];
                af[mi][1] = *(const uint32_t*)&a_s[(r0 + 8) * HSTR + k0 + 2 * tg];
                af[mi][2] = *(const uint32_t*)&a_s[r0 * HSTR + k0 + 8 + 2 * tg];
                af[mi][3] = *(const uint32_t*)&a_s[(r0 + 8) * HSTR + k0 + 8 + 2 * tg];
            }
#pragma unroll
            for (int ni = 0; ni < 4; ni++) {
                const int c0 = wn + ni * 8 + g;
                bf[ni][0] = *(const uint32_t*)&b_s[c0 * HSTR + k0 + 2 * tg];
                bf[ni][1] = *(const uint32_t*)&b_s[c0 * HSTR + k0 + 8 + 2 * tg];
            }
#pragma unroll
            for (int mi = 0; mi < 4; mi++)
#pragma unroll
                for (int ni = 0; ni < 4; ni++)
                    mma_f16(acc[mi][ni], af[mi], bf[ni]);
        }
        if (++st == 3) st = 0;
    }

#pragma unroll
    for (int mi = 0; mi < 4; mi++) {
        const int row = bm + wm + mi * 16 + g;
#pragma unroll
        for (int ni = 0; ni < 4; ni++) {
            const int col = bn + wn + ni * 8 + 2 * tg;
            const float bx = bias[col], by = bias[col + 1];
            float2 v0 = make_float2(acc[mi][ni][0] + bx, acc[mi][ni][1] + by);
            float2 v1 = make_float2(acc[mi][ni][2] + bx, acc[mi][ni][3] + by);
            *(float2*)&C[(size_t)row * N + col] = v0;
            *(float2*)&C[(size_t)(row + 8) * N + col] = v1;
        }
    }
}

__device__ __forceinline__ float silu_f(float x) {
    return x / (1.f + expf(-x));
}

// ---------------------------------------------------------------------------
// trig table
// ---------------------------------------------------------------------------
__global__ __launch_bounds__(256)
void trig_kernel(const float* __restrict__ theta)
{
    const int idx = blockIdx.x * 256 + threadIdx.x;
    const int d = idx & 63;
    const int n = (idx >> 6) & 2047;
    const int h = idx >> 17;
    float sn, cs;
    sincosf(theta[h * DH + d] * (float)n, &sn, &cs);
    g_trig[idx] = make_float2(cs, sn);
}

// ---------------------------------------------------------------------------
// partial KV via fp16 mma: per (bh, chunk of 256 tokens):
// C[dd][e] += k'T[dd][tok] * vT[e][tok]  (mma row.col, K=16 tokens/step)
// ---------------------------------------------------------------------------
#define KSTR 24

__global__ __launch_bounds__(256)
void kv_kernel()
{
    __shared__ __half skqT[128][KSTR];   // k'T [dd][tok]
    __shared__ __half svT[64][KSTR];     // vT  [e][tok]

    const int bh = blockIdx.x;
    const int b = bh >> 4, h = bh & 15;
    const int chunk = blockIdx.y;
    const int tid = threadIdx.x;
    const int wid = tid >> 5, lane = tid & 31;
    const int g = lane >> 2, tg = lane & 3;
    const int wm = (wid >> 1) * 32;      // dd: 0,32,64,96
    const int wn = (wid & 1) * 32;       // e : 0,32

    const float* base = g_qkvu + (size_t)b * Nn * 4096;
    const float2* trig = g_trig + (size_t)h * Nn * DH;

    float acc[2][4][4];
#pragma unroll
    for (int mi = 0; mi < 2; mi++)
#pragma unroll
        for (int ni = 0; ni < 4; ni++)
#pragma unroll
            for (int j = 0; j < 4; j++) acc[mi][ni][j] = 0.f;

    for (int n0 = chunk * 256; n0 < chunk * 256 + 256; n0 += 16) {
        __syncthreads();
#pragma unroll
        for (int it = 0; it < 4; it++) {
            const int item = tid + it * 256;     // 0..1023
            const int tok = item >> 6;
            const int d = item & 63;
            const int n = n0 + tok;
            const float kraw = base[(size_t)n * 4096 + Dd + h * DH + d];
            const float s = silu_f(kraw);
            const float2 t = trig[(size_t)n * DH + d];
            skqT[d][tok] = __float2half(s * t.x);
            skqT[DH + d][tok] = __float2half(s * t.y);
            svT[d][tok] = __float2half(base[(size_t)n * 4096 + 2 * Dd + h * DH + d]);
        }
        __syncthreads();

        uint32_t af[2][4], bf[4][2];
#pragma unroll
        for (int mi = 0; mi < 2; mi++) {
            const int r0 = wm + mi * 16 + g;
            af[mi][0] = *(const uint32_t*)&skqT[r0][2 * tg];
            af[mi][1] = *(const uint32_t*)&skqT[r0 + 8][2 * tg];
            af[mi][2] = *(const uint32_t*)&skqT[r0][8 + 2 * tg];
            af[mi][3] = *(const uint32_t*)&skqT[r0 + 8][8 + 2 * tg];
        }
#pragma unroll
        for (int ni = 0; ni < 4; ni++) {
            const int c0 = wn + ni * 8 + g;
            bf[ni][0] = *(const uint32_t*)&svT[c0][2 * tg];
            bf[ni][1] = *(const uint32_t*)&svT[c0][8 + 2 * tg];
        }
#pragma unroll
        for (int mi = 0; mi < 2; mi++)
#pragma unroll
            for (int ni = 0; ni < 4; ni++)
                mma_f16(acc[mi][ni], af[mi], bf[ni]);
    }

    // write partials transposed [e][dd] (fp32, deterministic reduce after)
    float* outp = g_kvp + (size_t)chunk * (32 * 8192) + (size_t)bh * 8192;
#pragma unroll
    for (int mi = 0; mi < 2; mi++) {
        const int dd0 = wm + mi * 16 + g;
#pragma unroll
        for (int ni = 0; ni < 4; ni++) {
            const int e0 = wn + ni * 8 + 2 * tg;
            outp[e0 * 128 + dd0]           = acc[mi][ni][0];
            outp[(e0 + 1) * 128 + dd0]     = acc[mi][ni][1];
            outp[e0 * 128 + dd0 + 8]       = acc[mi][ni][2];
            outp[(e0 + 1) * 128 + dd0 + 8] = acc[mi][ni][3];
        }
    }
}

__global__ __launch_bounds__(256)
void kv_reduce()
{
    const int i = blockIdx.x * 256 + threadIdx.x;
    float s = 0.f;
#pragma unroll
    for (int c = 0; c < 8; c++)
        s += g_kvp[(size_t)c * (32 * 8192) + i];
    g_kvTh[i] = __float2half(s);
}

// ---------------------------------------------------------------------------
// qout (fp16 mma): attn[tok, h*64+e] = sum_dd q'[tok,dd] * KVT[e,dd]
// ---------------------------------------------------------------------------
#define QH 136
#define QOUT_SMEM ((128 + 64) * QH * 2)   // 52224 B

__global__ __launch_bounds__(256)
void qout_kernel()
{
    extern __shared__ __half qsmh[];
    __half* sQh = qsmh;                  // [128 tok][QH]
    __half* sKVth = qsmh + 128 * QH;     // [64 e][QH]

    const int bh = blockIdx.x;
    const int b = bh >> 4, h = bh & 15;
    const int n0 = blockIdx.y * 128;
    const int tid = threadIdx.x;
    const int wid = tid >> 5, lane = tid & 31;
    const int g = lane >> 2, tg = lane & 3;

    {
        const uint4* src = (const uint4*)(g_kvTh + (size_t)bh * 8192);
        for (int i = tid; i < 1024; i += 256) {
            const int e = i >> 4;
            const int dc = (i & 15) * 8;
            *(uint4*)&sKVth[e * QH + dc] = src[i];
        }
    }

    {
        const int token = tid >> 1;
        const int d0 = (tid & 1) * 32;
        const int n = n0 + token;
        const float* qrow = g_qkvu + ((size_t)b * Nn + n) * 4096 + h * DH + d0;
        const float2* trow = g_trig + ((size_t)h * Nn + n) * DH + d0;
        __half* dst = sQh + token * QH;
#pragma unroll
        for (int d = 0; d < 32; d += 2) {
            const float s0 = silu_f(qrow[d]);
            const float s1 = silu_f(qrow[d + 1]);
            const float2 t0 = trow[d];
            const float2 t1 = trow[d + 1];
            *(__half2*)&dst[d0 + d] = __floats2half2_rn(s0 * t0.x, s1 * t1.x);
            *(__half2*)&dst[DH + d0 + d] = __floats2half2_rn(s0 * t0.y, s1 * t1.y);
        }
    }
    __syncthreads();

    const int wm = (wid >> 1) * 32;
    const int wn = (wid & 1) * 32;

    float acc[2][4][4];
#pragma unroll
    for (int mi = 0; mi < 2; mi++)
#pragma unroll
        for (int ni = 0; ni < 4; ni++)
#pragma unroll
            for (int j = 0; j < 4; j++) acc[mi][ni][j] = 0.f;

#pragma unroll
    for (int k0 = 0; k0 < 128; k0 += 16) {
        uint32_t af[2][4], bf[4][2];
#pragma unroll
        for (int mi = 0; mi < 2; mi++) {
            const int r0 = wm + mi * 16 + g;
            af[mi][0] = *(const uint32_t*)&sQh[r0 * QH + k0 + 2 * tg];
            af[mi][1] = *(const uint32_t*)&sQh[(r0 + 8) * QH + k0 + 2 * tg];
            af[mi][2] = *(const uint32_t*)&sQh[r0 * QH + k0 + 8 + 2 * tg];
            af[mi][3] = *(const uint32_t*)&sQh[(r0 + 8) * QH + k0 + 8 + 2 * tg];
        }
#pragma unroll
        for (int ni = 0; ni < 4; ni++) {
            const int c0 = wn + ni * 8 + g;
            bf[ni][0] = *(const uint32_t*)&sKVth[c0 * QH + k0 + 2 * tg];
            bf[ni][1] = *(const uint32_t*)&sKVth[c0 * QH + k0 + 8 + 2 * tg];
        }
#pragma unroll
        for (int mi = 0; mi < 2; mi++)
#pragma unroll
            for (int ni = 0; ni < 4; ni++)
                mma_f16(acc[mi][ni], af[mi], bf[ni]);
    }

#pragma unroll
    for (int mi = 0; mi < 2; mi++) {
        const int row = n0 + wm + mi * 16 + g;
        float* base0 = g_attn + ((size_t)b * Nn + row) * Dd + h * DH;
        float* base1 = g_attn + ((size_t)b * Nn + row + 8) * Dd + h * DH;
#pragma unroll
        for (int ni = 0; ni < 4; ni++) {
            const int col = wn + ni * 8 + 2 * tg;
            *(float2*)&base0[col] = make_float2(acc[mi][ni][0], acc[mi][ni][1]);
            *(float2*)&base1[col] = make_float2(acc[mi][ni][2], acc[mi][ni][3]);
        }
    }
}

// ---------------------------------------------------------------------------
// LayerNorm + *u ; emits fp16 for GEMM2
// ---------------------------------------------------------------------------
__device__ __forceinline__ float block_reduce_256(float v, float* sred, int tid)
{
#pragma unroll
    for (int o = 16; o; o >>= 1) v += __shfl_xor_sync(0xffffffffu, v, o);
    if ((tid & 31) == 0) sred[tid >> 5] = v;
    __syncthreads();
    float r;
    if (tid < 32) {
        float t = (tid < 8) ? sred[tid] : 0.f;
#pragma unroll
        for (int o = 4; o; o >>= 1) t += __shfl_xor_sync(0xffffffffu, t, o);
        if (tid == 0) sred[0] = t;
    }
    __syncthreads();
    r = sred[0];
    __syncthreads();
    return r;
}

__global__ __launch_bounds__(256)
void ln_kernel(const float* __restrict__ ln_w, const float* __restrict__ ln_b)
{
    __shared__ float sred[8];
    const int row = blockIdx.x;
    const int tid = threadIdx.x;
    const int b = row >> 11, n = row & 2047;

    const float4 v = ((const float4*)(g_attn + (size_t)row * Dd))[tid];
    float s = v.x + v.y + v.z + v.w;
    const float mu = block_reduce_256(s, sred, tid) * (1.f / 1024.f);

    const float dx = v.x - mu, dy = v.y - mu, dz = v.z - mu, dw = v.w - mu;
    float s2 = dx * dx + dy * dy + dz * dz + dw * dw;
    const float var = block_reduce_256(s2, sred, tid) * (1.f / 1024.f);
    const float rstd = rsqrtf(var + 1e-5f);

    const float4 w4 = ((const float4*)ln_w)[tid];
    const float4 b4 = ((const float4*)ln_b)[tid];
    const float4 u4 = ((const float4*)(g_qkvu + ((size_t)b * Nn + n) * 4096 + 3 * Dd))[tid];

    const float ox = (dx * rstd * w4.x + b4.x) * u4.x;
    const float oy = (dy * rstd * w4.y + b4.y) * u4.y;
    const float oz = (dz * rstd * w4.z + b4.z) * u4.z;
    const float ow = (dw * rstd * w4.w + b4.w) * u4.w;

    __half2* dsth = (__half2*)(g_normh + (size_t)row * Dd);
    dsth[2 * tid]     = __floats2half2_rn(ox, oy);
    dsth[2 * tid + 1] = __floats2half2_rn(oz, ow);
}

// ---------------------------------------------------------------------------
extern "C" void kernel_launch(void* const* d_in, const int* in_sizes, int n_in,
                              void* d_out, int out_size)
{
    const float* x     = (const float*)d_in[0];
    const float* Wqkvu = (const float*)d_in[2];
    const float* bqkvu = (const float*)d_in[3];
    const float* Wout  = (const float*)d_in[4];
    const float* bout  = (const float*)d_in[5];
    const float* theta = (const float*)d_in[6];
    const float* ln_w  = (const float*)d_in[7];
    const float* ln_b  = (const float*)d_in[8];
    float* out = (float*)d_out;

    float *qkvu_p;
    __half *xh_p, *wqh_p, *woh_p, *normh_p;
    cudaGetSymbolAddress((void**)&qkvu_p, g_qkvu);
    cudaGetSymbolAddress((void**)&xh_p, g_xh);
    cudaGetSymbolAddress((void**)&wqh_p, g_wqh);
    cudaGetSymbolAddress((void**)&woh_p, g_woh);
    cudaGetSymbolAddress((void**)&normh_p, g_normh);

    cudaFuncSetAttribute(qout_kernel, cudaFuncAttributeMaxDynamicSharedMemorySize,
                         QOUT_SMEM);
    cudaFuncSetAttribute(hgemm_nt, cudaFuncAttributeMaxDynamicSharedMemorySize,
                         H_SMEM_TOTAL);

    // 0. trig table + fp16 conversion of GEMM operands
    trig_kernel<<<(Hh * Nn * DH) / 256, 256>>>(theta);
    tohalf_kernel<<<(MROWS * Dd / 4 + 255) / 256, 256>>>((const float4*)x, (__half2*)xh_p, MROWS * Dd / 4);
    tohalf_kernel<<<(4 * Dd * Dd / 4 + 255) / 256, 256>>>((const float4*)Wqkvu, (__half2*)wqh_p, 4 * Dd * Dd / 4);
    tohalf_kernel<<<(Dd * Dd / 4 + 255) / 256, 256>>>((const float4*)Wout, (__half2*)woh_p, Dd * Dd / 4);

    // 1. qkvu = x @ Wqkvu^T + bqkvu   [4096 x 4096]  (fp16 mma, 3-stage)
    {
        dim3 grid(4096 / 128, MROWS / 128);
        hgemm_nt<<<grid, 256, H_SMEM_TOTAL>>>(xh_p, wqh_p, bqkvu, qkvu_p, MROWS, 4096, 1024);
    }
    // 2-3. KV^T partials (fp16 mma) + deterministic reduce -> fp16
    {
        dim3 grid(32, 8);
        kv_kernel<<<grid, 256>>>();
        kv_reduce<<<1024, 256>>>();
    }
    // 4. attn = q' @ KV  (fp16 mma)
    {
        dim3 grid(32, Nn / 128);
        qout_kernel<<<grid, 256, QOUT_SMEM>>>();
    }
    // 5. LayerNorm + *u -> fp16
    ln_kernel<<<MROWS, 256>>>(ln_w, ln_b);

    // 6. out = norm @ Wout^T + bout   [4096 x 1024]  (fp16 mma, 3-stage)
    {
        dim3 grid(1024 / 128, MROWS / 128);
        hgemm_nt<<<grid, 256, H_SMEM_TOTAL>>>(normh_p, woh_p, bout, out, MROWS, 1024, 1024);
    }
}